// round 3
// baseline (speedup 1.0000x reference)
#include <cuda_runtime.h>
#include <math.h>

#define BB 2
#define HH 128
#define WW 128
#define CC 128
#define NBR 9
#define HID 128
#define TP 16                 // positions per CTA
#define MROWS (TP*NBR)        // 144 edge rows per CTA
#define ASTR 130              // smem row stride (floats), even for u64 loads, odd/32 residue for banks
#define BSTR 130

typedef unsigned long long u64;

// ---------------- device scratch (allocation-free rule: __device__ globals) ----------------
__device__ float g_norm[BB*HH*WW*CC];      // LN1 output, 16.8 MB
__device__ float g_W3[CC*384];             // [c2][ Pn_d(128) | Pn_r(128) | vW(128) ]
__device__ float g_Wc[CC*256];             // [c ][ Pc_d(128) | Pc_r(128) ]
__device__ float g_reld[NBR*HID];          // rel@W1d + b1 (drive)
__device__ float g_relr[NBR*HID];          // rel@W1d + b1 (resistance)

struct SmemLayout {
  float A[MROWS*ASTR];       // gathered nbhd tile, [m][k]
  float Bm[CC*BSTR];         // weight tile transposed, [j][k]
  float center[TP*CC];       // normalized center rows
  float cterm[2][TP*HID];    // center pre-activation terms (d, r)
  float drive[TP*NBR];
  float res[TP*NBR];
  float gate[TP*NBR];
  float gsum[TP];
  float msg[TP*CC];
};
#define SMEM_BYTES ((int)sizeof(SmemLayout))

// -------- packed fp32x2 FMA (sm_103a; doubles FFMA throughput; pair over K) --------
__device__ __forceinline__ u64 fma2(u64 a, u64 b, u64 c){
  u64 d;
  asm("fma.rn.f32x2 %0, %1, %2, %3;" : "=l"(d) : "l"(a), "l"(b), "l"(c));
  return d;
}
__device__ __forceinline__ float pairsum(u64 v){
  union { u64 u; float2 f; } cv; cv.u = v;
  return cv.f.x + cv.f.y;
}

// ---------------- weight preprocessing ----------------
__global__ void prep_kernel(const float* __restrict__ dW1, const float* __restrict__ rW1,
                            const float* __restrict__ vW,  const float* __restrict__ rel,
                            const float* __restrict__ db1, const float* __restrict__ rb1)
{
  int idx = blockIdx.x*blockDim.x + threadIdx.x;
  if (idx < CC*384){
    int k = idx / 384, j = idx - k*384;
    float v;
    if (j < 128)       v = dW1[(128+k)*HID + j]       - dW1[(256+k)*HID + j];
    else if (j < 256)  v = rW1[(128+k)*HID + (j-128)] - rW1[(256+k)*HID + (j-128)];
    else               v = vW[k*CC + (j-256)];
    g_W3[idx] = v;
    return;
  }
  idx -= CC*384;
  if (idx < CC*256){
    int k = idx / 256, j = idx - k*256;
    float v;
    if (j < 128) v = dW1[k*HID + j]       + dW1[(256+k)*HID + j];
    else         v = rW1[k*HID + (j-128)] + rW1[(256+k)*HID + (j-128)];
    g_Wc[idx] = v;
    return;
  }
  idx -= CC*256;
  if (idx < 2*NBR*HID){
    int which = idx / (NBR*HID);
    int r = idx - which*(NBR*HID);
    int n = r / HID, hcol = r - n*HID;
    const float* W1 = which ? rW1 : dW1;
    const float* bb = which ? rb1 : db1;
    float acc = bb[hcol];
    #pragma unroll
    for (int p = 0; p < 8; ++p) acc += rel[n*8+p] * W1[(384+p)*HID + hcol];
    if (which) g_relr[r] = acc; else g_reld[r] = acc;
  }
}

// ---------------- LN1 ----------------
__global__ void ln1_kernel(const float* __restrict__ tokens,
                           const float* __restrict__ g, const float* __restrict__ b)
{
  int warp = (blockIdx.x*blockDim.x + threadIdx.x) >> 5;
  int lane = threadIdx.x & 31;
  if (warp >= BB*HH*WW) return;
  const float4 v = ((const float4*)(tokens + (size_t)warp*CC))[lane];
  float s = v.x + v.y + v.z + v.w;
  #pragma unroll
  for (int o = 16; o; o >>= 1) s += __shfl_xor_sync(0xffffffffu, s, o);
  float mean = s * (1.f/128.f);
  float dx=v.x-mean, dy=v.y-mean, dz=v.z-mean, dw=v.w-mean;
  float q = dx*dx + dy*dy + dz*dz + dw*dw;
  #pragma unroll
  for (int o = 16; o; o >>= 1) q += __shfl_xor_sync(0xffffffffu, q, o);
  float rs = rsqrtf(q*(1.f/128.f) + 1e-5f);
  float4 gg = ((const float4*)g)[lane];
  float4 bb = ((const float4*)b)[lane];
  float4 o4 = make_float4(dx*rs*gg.x+bb.x, dy*rs*gg.y+bb.y, dz*rs*gg.z+bb.z, dw*rs*gg.w+bb.w);
  ((float4*)(g_norm + (size_t)warp*CC))[lane] = o4;
}

// ---------------- helpers for the main fused kernel ----------------
__device__ __forceinline__ void load_Bm(SmemLayout& S, const float* __restrict__ src,
                                        int srcStride, int srcOff, int t)
{
  // Bm[j][k] = src[k][srcOff + j]; coalesced global read, ~2-way smem write conflict
  #pragma unroll 4
  for (int it = 0; it < 32; ++it){
    int e = it*512 + t;
    int k = e >> 7, j = e & 127;
    S.Bm[j*BSTR + k] = src[k*srcStride + srcOff + j];
  }
}

// 9-row x 4-col register tile GEMM: rows m = ty*9+i, cols j = tx + jj*32, K=128 paired
__device__ __forceinline__ void gemm_row9(const SmemLayout& S, int ty, int tx, float res[NBR][4])
{
  u64 acc[NBR][4];
  #pragma unroll
  for (int i = 0; i < NBR; ++i)
    #pragma unroll
    for (int jj = 0; jj < 4; ++jj) acc[i][jj] = 0ull;
  const float* ap = &S.A[(ty*9)*ASTR];
  const float* bp = &S.Bm[tx*BSTR];
  #pragma unroll 4
  for (int k = 0; k < CC; k += 2){
    u64 b2[4];
    #pragma unroll
    for (int jj = 0; jj < 4; ++jj)
      b2[jj] = *reinterpret_cast<const u64*>(bp + (jj*32)*BSTR + k);
    #pragma unroll
    for (int i = 0; i < NBR; ++i){
      u64 a2 = *reinterpret_cast<const u64*>(ap + i*ASTR + k);
      #pragma unroll
      for (int jj = 0; jj < 4; ++jj)
        acc[i][jj] = fma2(a2, b2[jj], acc[i][jj]);
    }
  }
  #pragma unroll
  for (int i = 0; i < NBR; ++i)
    #pragma unroll
    for (int jj = 0; jj < 4; ++jj) res[i][jj] = pairsum(acc[i][jj]);
}

// 1-row x 4-col GEMM (center term / output projection)
__device__ __forceinline__ void gemm_row1(const SmemLayout& S, const float* __restrict__ ap,
                                          int tx, float res[4])
{
  u64 acc[4] = {0ull,0ull,0ull,0ull};
  const float* bp = &S.Bm[tx*BSTR];
  #pragma unroll 8
  for (int k = 0; k < CC; k += 2){
    u64 a2 = *reinterpret_cast<const u64*>(ap + k);
    #pragma unroll
    for (int jj = 0; jj < 4; ++jj)
      acc[jj] = fma2(a2, *reinterpret_cast<const u64*>(bp + (jj*32)*BSTR + k), acc[jj]);
  }
  #pragma unroll
  for (int jj = 0; jj < 4; ++jj) res[jj] = pairsum(acc[jj]);
}

// ---------------- main fused kernel: one CTA = 16 positions of one (b, h) row ----------------
__global__ void __launch_bounds__(512, 1) eml_main(
    const float* __restrict__ tokens,
    const float* __restrict__ dW2, const float* __restrict__ db2,
    const float* __restrict__ rW2, const float* __restrict__ rb2,
    const float* __restrict__ vb,  const float* __restrict__ oW,
    const float* __restrict__ ob,  const float* __restrict__ ln2g,
    const float* __restrict__ ln2b,
    const float* __restrict__ gamp, const float* __restrict__ lamp,
    const float* __restrict__ biasp,
    float* __restrict__ out)
{
  extern __shared__ float smraw[];
  SmemLayout& S = *reinterpret_cast<SmemLayout*>(smraw);
  const int t  = threadIdx.x;
  const int ty = t >> 5;      // position within tile (0..15)
  const int tx = t & 31;      // column lane
  const int w0 = blockIdx.x * TP;
  const int h  = blockIdx.y;
  const int b  = blockIdx.z;

  // ---- Stage A: gather 9 shifted rows per position, scatter through the torch-reshape bijection ----
  #pragma unroll 2
  for (int it = 0; it < 36; ++it){          // 144 rows * 128 ch / 512 threads
    int e  = it*512 + t;
    int ch = e & 127;
    int ps = e >> 7;
    int p  = ps / 9, s = ps - p*9;
    int hh = h + (s/3) - 1;
    int ww = w0 + p + (s - (s/3)*3) - 1;
    float v = 0.f;
    if ((unsigned)hh < HH && (unsigned)ww < WW)
      v = g_norm[(((b*HH + hh)*WW + ww) << 7) + ch];
    int q = ch*9 + s;                        // (s,ch) -> (n,c2)
    S.A[(p*9 + (q >> 7))*ASTR + (q & 127)] = v;
  }
  for (int it = 0; it < 4; ++it){
    int e = it*512 + t;
    int p = e >> 7, ch = e & 127;
    S.center[e] = g_norm[(((b*HH + h)*WW + (w0+p)) << 7) + ch];
  }
  __syncthreads();

  // ---- Center pre-activation terms (per position, not per edge) ----
  for (int half = 0; half < 2; ++half){
    load_Bm(S, g_Wc, 256, half*128, t);
    __syncthreads();
    float cres[4];
    gemm_row1(S, &S.center[ty*CC], tx, cres);
    #pragma unroll
    for (int jj = 0; jj < 4; ++jj)
      S.cterm[half][ty*HID + tx + jj*32] = cres[jj];
    __syncthreads();
  }

  // ---- Drive / Resistance: nbhd-term GEMM + GELU + dot(W2) + cross-lane reduce ----
  for (int chunk = 0; chunk < 2; ++chunk){
    load_Bm(S, g_W3, 384, chunk*128, t);
    __syncthreads();
    float res9[NBR][4];
    gemm_row9(S, ty, tx, res9);

    const float* W2   = chunk ? rW2 : dW2;
    const float* relb = chunk ? g_relr : g_reld;
    float w2v[4];
    #pragma unroll
    for (int jj = 0; jj < 4; ++jj) w2v[jj] = W2[tx + jj*32];
    const float* ct = &S.cterm[chunk][ty*HID];

    #pragma unroll
    for (int i = 0; i < NBR; ++i){
      float sum = 0.f;
      #pragma unroll
      for (int jj = 0; jj < 4; ++jj){
        int hcol = tx + jj*32;
        float x = res9[i][jj] + ct[hcol] + relb[i*HID + hcol];
        float gel = 0.5f * x * (1.f + erff(x * 0.70710678118654752f));
        sum += gel * w2v[jj];
      }
      #pragma unroll
      for (int o = 16; o; o >>= 1) sum += __shfl_xor_sync(0xffffffffu, sum, o);
      if (tx == 0){
        float b2s = chunk ? rb2[0] : db2[0];
        (chunk ? S.res : S.drive)[ty*NBR + i] = sum + b2s;
      }
    }
    __syncthreads();
  }

  // ---- EML gate ----
  if (t < TP*NBR){
    float d = S.drive[t], r = S.res[t];
    float sp = (r > 20.f) ? r : log1pf(expf(r));
    float e = (gamp[0] * d) / (lamp[0] * sp + 1e-6f) + biasp[0];
    e = fminf(3.f, fmaxf(-3.f, e));
    S.gate[t] = 1.f / (1.f + expf(-e));
  }
  __syncthreads();
  if (t < TP){
    float s = 0.f;
    #pragma unroll
    for (int n = 0; n < NBR; ++n) s += S.gate[t*NBR + n];
    S.gsum[t] = s;
  }
  __syncthreads();

  // ---- Values GEMM + gated message ----
  {
    load_Bm(S, g_W3, 384, 256, t);
    __syncthreads();
    float val9[NBR][4];
    gemm_row9(S, ty, tx, val9);

    float gsum = S.gsum[ty];
    float inv  = 1.f / fmaxf(gsum, 1e-6f);
    float gt[NBR];
    #pragma unroll
    for (int i = 0; i < NBR; ++i) gt[i] = S.gate[ty*NBR + i];
    #pragma unroll
    for (int jj = 0; jj < 4; ++jj){
      int c = tx + jj*32;
      float acv = 0.f;
      #pragma unroll
      for (int i = 0; i < NBR; ++i) acv += gt[i] * val9[i][jj];
      S.msg[ty*CC + c] = (acv + gsum * vb[c]) * inv;
    }
    __syncthreads();
  }

  // ---- Output projection + residual + LN2 ----
  {
    load_Bm(S, oW, CC, 0, t);
    __syncthreads();
    float upd[4];
    gemm_row1(S, &S.msg[ty*CC], tx, upd);

    const int base = (((b*HH + h)*WW + (w0 + ty)) << 7);
    float u[4], ssum = 0.f, ssq = 0.f;
    #pragma unroll
    for (int jj = 0; jj < 4; ++jj){
      int c = tx + jj*32;
      u[jj] = tokens[base + c] + upd[jj] + ob[c];
      ssum += u[jj];
      ssq  += u[jj]*u[jj];
    }
    #pragma unroll
    for (int o = 16; o; o >>= 1){
      ssum += __shfl_xor_sync(0xffffffffu, ssum, o);
      ssq  += __shfl_xor_sync(0xffffffffu, ssq,  o);
    }
    float mean = ssum * (1.f/128.f);
    float var  = ssq * (1.f/128.f) - mean*mean;
    float rs   = rsqrtf(var + 1e-5f);
    #pragma unroll
    for (int jj = 0; jj < 4; ++jj){
      int c = tx + jj*32;
      out[base + c] = (u[jj] - mean) * rs * ln2g[c] + ln2b[c];
    }
  }
}

// ---------------- launcher ----------------
extern "C" void kernel_launch(void* const* d_in, const int* in_sizes, int n_in,
                              void* d_out, int out_size)
{
  const float* tokens = (const float*)d_in[0];
  const float* ln1g   = (const float*)d_in[1];
  const float* ln1b   = (const float*)d_in[2];
  const float* ln2g   = (const float*)d_in[3];
  const float* ln2b   = (const float*)d_in[4];
  const float* rel    = (const float*)d_in[5];
  const float* dW1    = (const float*)d_in[6];
  const float* db1    = (const float*)d_in[7];
  const float* dW2    = (const float*)d_in[8];
  const float* db2    = (const float*)d_in[9];
  const float* rW1    = (const float*)d_in[10];
  const float* rb1    = (const float*)d_in[11];
  const float* rW2    = (const float*)d_in[12];
  const float* rb2    = (const float*)d_in[13];
  const float* vW     = (const float*)d_in[14];
  const float* vb     = (const float*)d_in[15];
  const float* oW     = (const float*)d_in[16];
  const float* ob     = (const float*)d_in[17];
  const float* gam    = (const float*)d_in[18];
  const float* lam    = (const float*)d_in[19];
  const float* bias   = (const float*)d_in[20];

  cudaFuncSetAttribute(eml_main, cudaFuncAttributeMaxDynamicSharedMemorySize, SMEM_BYTES);

  {
    int total = CC*384 + CC*256 + 2*NBR*HID;
    prep_kernel<<<(total + 255)/256, 256>>>(dW1, rW1, vW, rel, db1, rb1);
  }
  ln1_kernel<<<(BB*HH*WW)/16, 512>>>(tokens, ln1g, ln1b);

  dim3 grid(WW/TP, HH, BB);
  eml_main<<<grid, 512, SMEM_BYTES>>>(tokens, dW2, db2, rW2, rb2, vb, oW, ob,
                                      ln2g, ln2b, gam, lam, bias, (float*)d_out);
}

// round 4
// speedup vs baseline: 1.6053x; 1.6053x over previous
#include <cuda_runtime.h>
#include <math.h>

#define BB 2
#define HH 128
#define WW 128
#define CC 128
#define NBR 9
#define HID 128
#define TP 16                 // positions per CTA
#define MROWS (TP*NBR)        // 144 edge rows per CTA
#define ASTR 130              // smem row stride (floats), even for u64 loads, odd/32 residue for banks
#define BSTR 130

typedef unsigned long long u64;

// ---------------- device scratch (allocation-free rule: __device__ globals) ----------------
__device__ float g_norm[BB*HH*WW*CC];      // LN1 output, 16.8 MB
__device__ float g_W3[CC*384];             // [c2][ Pn_d(128) | Pn_r(128) | vW(128) ]
__device__ float g_Wc[CC*256];             // [c ][ Pc_d(128) | Pc_r(128) ]
__device__ float g_reld[NBR*HID];          // rel@W1d + b1 (drive)
__device__ float g_relr[NBR*HID];          // rel@W1d + b1 (resistance)

struct SmemLayout {
  float A[MROWS*ASTR];       // gathered nbhd tile, [m][k]
  float Bm[CC*BSTR];         // weight tile transposed, [j][k]
  float center[TP*CC];       // normalized center rows
  float cterm[2][TP*HID];    // center pre-activation terms (d, r)
  float drive[TP*NBR];
  float res[TP*NBR];
  float gate[TP*NBR];
  float gsum[TP];
  float msg[TP*CC];
};
#define SMEM_BYTES ((int)sizeof(SmemLayout))

// -------- packed fp32x2 FMA (sm_103a; doubles FFMA throughput; pair over K) --------
__device__ __forceinline__ u64 fma2(u64 a, u64 b, u64 c){
  u64 d;
  asm("fma.rn.f32x2 %0, %1, %2, %3;" : "=l"(d) : "l"(a), "l"(b), "l"(c));
  return d;
}
__device__ __forceinline__ float pairsum(u64 v){
  union { u64 u; float2 f; } cv; cv.u = v;
  return cv.f.x + cv.f.y;
}

// ---------------- weight preprocessing ----------------
__global__ void prep_kernel(const float* __restrict__ dW1, const float* __restrict__ rW1,
                            const float* __restrict__ vW,  const float* __restrict__ rel,
                            const float* __restrict__ db1, const float* __restrict__ rb1)
{
  int idx = blockIdx.x*blockDim.x + threadIdx.x;
  if (idx < CC*384){
    int k = idx / 384, j = idx - k*384;
    float v;
    if (j < 128)       v = dW1[(128+k)*HID + j]       - dW1[(256+k)*HID + j];
    else if (j < 256)  v = rW1[(128+k)*HID + (j-128)] - rW1[(256+k)*HID + (j-128)];
    else               v = vW[k*CC + (j-256)];
    g_W3[idx] = v;
    return;
  }
  idx -= CC*384;
  if (idx < CC*256){
    int k = idx / 256, j = idx - k*256;
    float v;
    if (j < 128) v = dW1[k*HID + j]       + dW1[(256+k)*HID + j];
    else         v = rW1[k*HID + (j-128)] + rW1[(256+k)*HID + (j-128)];
    g_Wc[idx] = v;
    return;
  }
  idx -= CC*256;
  if (idx < 2*NBR*HID){
    int which = idx / (NBR*HID);
    int r = idx - which*(NBR*HID);
    int n = r / HID, hcol = r - n*HID;
    const float* W1 = which ? rW1 : dW1;
    const float* bb = which ? rb1 : db1;
    float acc = bb[hcol];
    #pragma unroll
    for (int p = 0; p < 8; ++p) acc += rel[n*8+p] * W1[(384+p)*HID + hcol];
    if (which) g_relr[r] = acc; else g_reld[r] = acc;
  }
}

// ---------------- LN1 ----------------
__global__ void ln1_kernel(const float* __restrict__ tokens,
                           const float* __restrict__ g, const float* __restrict__ b)
{
  int warp = (blockIdx.x*blockDim.x + threadIdx.x) >> 5;
  int lane = threadIdx.x & 31;
  if (warp >= BB*HH*WW) return;
  const float4 v = ((const float4*)(tokens + (size_t)warp*CC))[lane];
  float s = v.x + v.y + v.z + v.w;
  #pragma unroll
  for (int o = 16; o; o >>= 1) s += __shfl_xor_sync(0xffffffffu, s, o);
  float mean = s * (1.f/128.f);
  float dx=v.x-mean, dy=v.y-mean, dz=v.z-mean, dw=v.w-mean;
  float q = dx*dx + dy*dy + dz*dz + dw*dw;
  #pragma unroll
  for (int o = 16; o; o >>= 1) q += __shfl_xor_sync(0xffffffffu, q, o);
  float rs = rsqrtf(q*(1.f/128.f) + 1e-5f);
  float4 gg = ((const float4*)g)[lane];
  float4 bb = ((const float4*)b)[lane];
  float4 o4 = make_float4(dx*rs*gg.x+bb.x, dy*rs*gg.y+bb.y, dz*rs*gg.z+bb.z, dw*rs*gg.w+bb.w);
  ((float4*)(g_norm + (size_t)warp*CC))[lane] = o4;
}

// ---------------- helpers for the main fused kernel ----------------
__device__ __forceinline__ void load_Bm(SmemLayout& S, const float* __restrict__ src,
                                        int srcStride, int srcOff, int t)
{
  // Bm[j][k] = src[k][srcOff + j]; coalesced global read, ~2-way smem write conflict
  #pragma unroll 4
  for (int it = 0; it < 32; ++it){
    int e = it*512 + t;
    int k = e >> 7, j = e & 127;
    S.Bm[j*BSTR + k] = src[k*srcStride + srcOff + j];
  }
}

// 9-row x 4-col register tile GEMM: rows m = ty*9+i, cols j = tx + jj*32, K=128 paired
__device__ __forceinline__ void gemm_row9(const SmemLayout& S, int ty, int tx, float res[NBR][4])
{
  u64 acc[NBR][4];
  #pragma unroll
  for (int i = 0; i < NBR; ++i)
    #pragma unroll
    for (int jj = 0; jj < 4; ++jj) acc[i][jj] = 0ull;
  const float* ap = &S.A[(ty*9)*ASTR];
  const float* bp = &S.Bm[tx*BSTR];
  #pragma unroll 4
  for (int k = 0; k < CC; k += 2){
    u64 b2[4];
    #pragma unroll
    for (int jj = 0; jj < 4; ++jj)
      b2[jj] = *reinterpret_cast<const u64*>(bp + (jj*32)*BSTR + k);
    #pragma unroll
    for (int i = 0; i < NBR; ++i){
      u64 a2 = *reinterpret_cast<const u64*>(ap + i*ASTR + k);
      #pragma unroll
      for (int jj = 0; jj < 4; ++jj)
        acc[i][jj] = fma2(a2, b2[jj], acc[i][jj]);
    }
  }
  #pragma unroll
  for (int i = 0; i < NBR; ++i)
    #pragma unroll
    for (int jj = 0; jj < 4; ++jj) res[i][jj] = pairsum(acc[i][jj]);
}

// 1-row x 4-col GEMM (center term / output projection)
__device__ __forceinline__ void gemm_row1(const SmemLayout& S, const float* __restrict__ ap,
                                          int tx, float res[4])
{
  u64 acc[4] = {0ull,0ull,0ull,0ull};
  const float* bp = &S.Bm[tx*BSTR];
  #pragma unroll 8
  for (int k = 0; k < CC; k += 2){
    u64 a2 = *reinterpret_cast<const u64*>(ap + k);
    #pragma unroll
    for (int jj = 0; jj < 4; ++jj)
      acc[jj] = fma2(a2, *reinterpret_cast<const u64*>(bp + (jj*32)*BSTR + k), acc[jj]);
  }
  #pragma unroll
  for (int jj = 0; jj < 4; ++jj) res[jj] = pairsum(acc[jj]);
}

// ---------------- main fused kernel: one CTA = 16 positions of one (b, h) row ----------------
__global__ void __launch_bounds__(512, 1) eml_main(
    const float* __restrict__ tokens,
    const float* __restrict__ dW2, const float* __restrict__ db2,
    const float* __restrict__ rW2, const float* __restrict__ rb2,
    const float* __restrict__ vb,  const float* __restrict__ oW,
    const float* __restrict__ ob,  const float* __restrict__ ln2g,
    const float* __restrict__ ln2b,
    const float* __restrict__ gamp, const float* __restrict__ lamp,
    const float* __restrict__ biasp,
    float* __restrict__ out)
{
  extern __shared__ float smraw[];
  SmemLayout& S = *reinterpret_cast<SmemLayout*>(smraw);
  const int t  = threadIdx.x;
  const int ty = t >> 5;      // position within tile (0..15)
  const int tx = t & 31;      // column lane
  const int w0 = blockIdx.x * TP;
  const int h  = blockIdx.y;
  const int b  = blockIdx.z;

  // ---- Stage A: gather 9 shifted rows per position, scatter through the torch-reshape bijection ----
  #pragma unroll 2
  for (int it = 0; it < 36; ++it){          // 144 rows * 128 ch / 512 threads
    int e  = it*512 + t;
    int ch = e & 127;
    int ps = e >> 7;
    int p  = ps / 9, s = ps - p*9;
    int hh = h + (s/3) - 1;
    int ww = w0 + p + (s - (s/3)*3) - 1;
    float v = 0.f;
    if ((unsigned)hh < HH && (unsigned)ww < WW)
      v = g_norm[(((b*HH + hh)*WW + ww) << 7) + ch];
    int q = ch*9 + s;                        // (s,ch) -> (n,c2)
    S.A[(p*9 + (q >> 7))*ASTR + (q & 127)] = v;
  }
  for (int it = 0; it < 4; ++it){
    int e = it*512 + t;
    int p = e >> 7, ch = e & 127;
    S.center[e] = g_norm[(((b*HH + h)*WW + (w0+p)) << 7) + ch];
  }
  __syncthreads();

  // ---- Center pre-activation terms (per position, not per edge) ----
  for (int half = 0; half < 2; ++half){
    load_Bm(S, g_Wc, 256, half*128, t);
    __syncthreads();
    float cres[4];
    gemm_row1(S, &S.center[ty*CC], tx, cres);
    #pragma unroll
    for (int jj = 0; jj < 4; ++jj)
      S.cterm[half][ty*HID + tx + jj*32] = cres[jj];
    __syncthreads();
  }

  // ---- Drive / Resistance: nbhd-term GEMM + GELU + dot(W2) + cross-lane reduce ----
  for (int chunk = 0; chunk < 2; ++chunk){
    load_Bm(S, g_W3, 384, chunk*128, t);
    __syncthreads();
    float res9[NBR][4];
    gemm_row9(S, ty, tx, res9);

    const float* W2   = chunk ? rW2 : dW2;
    const float* relb = chunk ? g_relr : g_reld;
    float w2v[4];
    #pragma unroll
    for (int jj = 0; jj < 4; ++jj) w2v[jj] = W2[tx + jj*32];
    const float* ct = &S.cterm[chunk][ty*HID];

    #pragma unroll
    for (int i = 0; i < NBR; ++i){
      float sum = 0.f;
      #pragma unroll
      for (int jj = 0; jj < 4; ++jj){
        int hcol = tx + jj*32;
        float x = res9[i][jj] + ct[hcol] + relb[i*HID + hcol];
        float gel = 0.5f * x * (1.f + erff(x * 0.70710678118654752f));
        sum += gel * w2v[jj];
      }
      #pragma unroll
      for (int o = 16; o; o >>= 1) sum += __shfl_xor_sync(0xffffffffu, sum, o);
      if (tx == 0){
        float b2s = chunk ? rb2[0] : db2[0];
        (chunk ? S.res : S.drive)[ty*NBR + i] = sum + b2s;
      }
    }
    __syncthreads();
  }

  // ---- EML gate ----
  if (t < TP*NBR){
    float d = S.drive[t], r = S.res[t];
    float sp = (r > 20.f) ? r : log1pf(expf(r));
    float e = (gamp[0] * d) / (lamp[0] * sp + 1e-6f) + biasp[0];
    e = fminf(3.f, fmaxf(-3.f, e));
    S.gate[t] = 1.f / (1.f + expf(-e));
  }
  __syncthreads();
  if (t < TP){
    float s = 0.f;
    #pragma unroll
    for (int n = 0; n < NBR; ++n) s += S.gate[t*NBR + n];
    S.gsum[t] = s;
  }
  __syncthreads();

  // ---- Values GEMM + gated message ----
  {
    load_Bm(S, g_W3, 384, 256, t);
    __syncthreads();
    float val9[NBR][4];
    gemm_row9(S, ty, tx, val9);

    float gsum = S.gsum[ty];
    float inv  = 1.f / fmaxf(gsum, 1e-6f);
    float gt[NBR];
    #pragma unroll
    for (int i = 0; i < NBR; ++i) gt[i] = S.gate[ty*NBR + i];
    #pragma unroll
    for (int jj = 0; jj < 4; ++jj){
      int c = tx + jj*32;
      float acv = 0.f;
      #pragma unroll
      for (int i = 0; i < NBR; ++i) acv += gt[i] * val9[i][jj];
      S.msg[ty*CC + c] = (acv + gsum * vb[c]) * inv;
    }
    __syncthreads();
  }

  // ---- Output projection + residual + LN2 ----
  {
    load_Bm(S, oW, CC, 0, t);
    __syncthreads();
    float upd[4];
    gemm_row1(S, &S.msg[ty*CC], tx, upd);

    const int base = (((b*HH + h)*WW + (w0 + ty)) << 7);
    float u[4], ssum = 0.f, ssq = 0.f;
    #pragma unroll
    for (int jj = 0; jj < 4; ++jj){
      int c = tx + jj*32;
      u[jj] = tokens[base + c] + upd[jj] + ob[c];
      ssum += u[jj];
      ssq  += u[jj]*u[jj];
    }
    #pragma unroll
    for (int o = 16; o; o >>= 1){
      ssum += __shfl_xor_sync(0xffffffffu, ssum, o);
      ssq  += __shfl_xor_sync(0xffffffffu, ssq,  o);
    }
    float mean = ssum * (1.f/128.f);
    float var  = ssq * (1.f/128.f) - mean*mean;
    float rs   = rsqrtf(var + 1e-5f);
    #pragma unroll
    for (int jj = 0; jj < 4; ++jj){
      int c = tx + jj*32;
      out[base + c] = (u[jj] - mean) * rs * ln2g[c] + ln2b[c];
    }
  }
}

// ---------------- launcher ----------------
extern "C" void kernel_launch(void* const* d_in, const int* in_sizes, int n_in,
                              void* d_out, int out_size)
{
  const float* tokens = (const float*)d_in[0];
  const float* ln1g   = (const float*)d_in[1];
  const float* ln1b   = (const float*)d_in[2];
  const float* ln2g   = (const float*)d_in[3];
  const float* ln2b   = (const float*)d_in[4];
  const float* rel    = (const float*)d_in[5];
  const float* dW1    = (const float*)d_in[6];
  const float* db1    = (const float*)d_in[7];
  const float* dW2    = (const float*)d_in[8];
  const float* db2    = (const float*)d_in[9];
  const float* rW1    = (const float*)d_in[10];
  const float* rb1    = (const float*)d_in[11];
  const float* rW2    = (const float*)d_in[12];
  const float* rb2    = (const float*)d_in[13];
  const float* vW     = (const float*)d_in[14];
  const float* vb     = (const float*)d_in[15];
  const float* oW     = (const float*)d_in[16];
  const float* ob     = (const float*)d_in[17];
  const float* gam    = (const float*)d_in[18];
  const float* lam    = (const float*)d_in[19];
  const float* bias   = (const float*)d_in[20];

  cudaFuncSetAttribute(eml_main, cudaFuncAttributeMaxDynamicSharedMemorySize, SMEM_BYTES);

  {
    int total = CC*384 + CC*256 + 2*NBR*HID;
    prep_kernel<<<(total + 255)/256, 256>>>(dW1, rW1, vW, rel, db1, rb1);
  }
  ln1_kernel<<<(BB*HH*WW)/16, 512>>>(tokens, ln1g, ln1b);

  dim3 grid(WW/TP, HH, BB);
  eml_main<<<grid, 512, SMEM_BYTES>>>(tokens, dW2, db2, rW2, rb2, vb, oW, ob,
                                      ln2g, ln2b, gam, lam, bias, (float*)d_out);
}